// round 1
// baseline (speedup 1.0000x reference)
#include <cuda_runtime.h>
#include <cuda_bf16.h>
#include <math.h>

#define NN 50000
#define EE 800000
#define HID 128
#define LAYERS 4

// ---------------- device scratch (no allocation allowed) ----------------
__device__ float g_xA[NN * HID];
__device__ float g_xB[NN * HID];
__device__ float g_xl[NN * HID];
__device__ float g_xr[NN * HID];
__device__ float g_WlT[LAYERS * HID * HID];
__device__ float g_WrT[LAYERS * HID * HID];
__device__ float g_WembT[11 * HID];
__device__ int g_deg[NN];
__device__ int g_rowptr[NN + 1];
__device__ int g_next[NN];
__device__ int g_csrc[EE];

// ---------------- weight transpose: W[j][k] -> Wt[k][j] ----------------
__global__ void k_prep(const float* __restrict__ Wemb,
                       const float* __restrict__ Wl,
                       const float* __restrict__ Wr) {
    int t = blockIdx.x * blockDim.x + threadIdx.x;
    const int per = LAYERS * HID * HID;
    if (t < per) {
        int l = t >> 14, r = t & 16383, j = r >> 7, k = r & 127;
        g_WlT[(l << 14) + k * HID + j] = Wl[t];
        g_WrT[(l << 14) + k * HID + j] = Wr[t];
    } else {
        int u = t - per;
        if (u < HID * 11) {
            int j = u / 11, k = u % 11;
            g_WembT[k * HID + j] = Wemb[u];
        }
    }
}

// ---------------- CSR build ----------------
__global__ void k_zero_deg() {
    int i = blockIdx.x * blockDim.x + threadIdx.x;
    if (i < NN) g_deg[i] = 0;
}
__global__ void k_hist(const int* __restrict__ ei) {
    int e = blockIdx.x * blockDim.x + threadIdx.x;
    if (e < EE) atomicAdd(&g_deg[ei[EE + e]], 1);
}
// one block, 1024 threads: exclusive scan of g_deg -> g_rowptr, copy to g_next
__global__ void k_scan() {
    __shared__ int ssum[1024];
    int tid = threadIdx.x;
    const int CH = (NN + 1023) / 1024;  // 49
    int base = tid * CH;
    int local = 0;
    for (int i = 0; i < CH; i++) {
        int idx = base + i;
        if (idx < NN) local += g_deg[idx];
    }
    ssum[tid] = local;
    __syncthreads();
    for (int off = 1; off < 1024; off <<= 1) {
        int v = 0;
        if (tid >= off) v = ssum[tid - off];
        __syncthreads();
        ssum[tid] += v;
        __syncthreads();
    }
    int run = (tid == 0) ? 0 : ssum[tid - 1];
    for (int i = 0; i < CH; i++) {
        int idx = base + i;
        if (idx < NN) {
            g_rowptr[idx] = run;
            g_next[idx] = run;
            run += g_deg[idx];
        }
    }
    if (tid == 1023) g_rowptr[NN] = run;
}
__global__ void k_scatter(const int* __restrict__ ei) {
    int e = blockIdx.x * blockDim.x + threadIdx.x;
    if (e < EE) {
        int d = ei[EE + e];
        int pos = atomicAdd(&g_next[d], 1);
        g_csrc[pos] = ei[e];
    }
}

// ---------------- embedding: x = relu(feat @ Wemb^T + b) ----------------
__global__ void k_embed(const float* __restrict__ feat,
                        const float* __restrict__ bemb,
                        float* __restrict__ xout) {
    int gid = blockIdx.x * blockDim.x + threadIdx.x;
    if (gid >= NN * HID) return;
    int n = gid >> 7, j = gid & 127;
    float a = bemb[j];
#pragma unroll
    for (int k = 0; k < 11; k++) a += feat[n * 11 + k] * g_WembT[k * HID + j];
    xout[gid] = fmaxf(a, 0.f);
}

// ---------------- GEMM: xl = x @ Wl^T + bl (and xr likewise) ----------------
// grid (ceil(N/64), 4): y<2 -> Wl halves, y>=2 -> Wr halves. 256 threads, 4x4/thread.
__global__ void k_gemm(const float* __restrict__ xin,
                       const float* __restrict__ bl,
                       const float* __restrict__ br,
                       int layer) {
    __shared__ float xs[16][65];
    __shared__ float ws[16][64];
    int n0 = blockIdx.x * 64;
    int jt = blockIdx.y;
    const float* Wt = ((jt < 2) ? g_WlT : g_WrT) + (layer << 14);
    float* outp = (jt < 2) ? g_xl : g_xr;
    const float* bp = ((jt < 2) ? bl : br) + layer * HID;
    int j0 = (jt & 1) * 64;
    int tid = threadIdx.x;
    int tx = tid & 15, ty = tid >> 4;
    float acc[4][4];
#pragma unroll
    for (int r = 0; r < 4; r++)
#pragma unroll
        for (int c = 0; c < 4; c++) acc[r][c] = 0.f;

    for (int kc = 0; kc < HID; kc += 16) {
#pragma unroll
        for (int u = 0; u < 4; u++) {
            int idx = tid + u * 256;
            int i = idx >> 4, kk = idx & 15;
            int n = n0 + i;
            xs[kk][i] = (n < NN) ? xin[n * HID + kc + kk] : 0.f;
            int kk2 = idx >> 6, jj = idx & 63;
            ws[kk2][jj] = Wt[(kc + kk2) * HID + j0 + jj];
        }
        __syncthreads();
#pragma unroll
        for (int kk = 0; kk < 16; kk++) {
            float a0 = xs[kk][ty * 4 + 0];
            float a1 = xs[kk][ty * 4 + 1];
            float a2 = xs[kk][ty * 4 + 2];
            float a3 = xs[kk][ty * 4 + 3];
            float4 b = *(const float4*)&ws[kk][tx * 4];
            acc[0][0] += a0 * b.x; acc[0][1] += a0 * b.y; acc[0][2] += a0 * b.z; acc[0][3] += a0 * b.w;
            acc[1][0] += a1 * b.x; acc[1][1] += a1 * b.y; acc[1][2] += a1 * b.z; acc[1][3] += a1 * b.w;
            acc[2][0] += a2 * b.x; acc[2][1] += a2 * b.y; acc[2][2] += a2 * b.z; acc[2][3] += a2 * b.w;
            acc[3][0] += a3 * b.x; acc[3][1] += a3 * b.y; acc[3][2] += a3 * b.z; acc[3][3] += a3 * b.w;
        }
        __syncthreads();
    }
#pragma unroll
    for (int r = 0; r < 4; r++) {
        int n = n0 + ty * 4 + r;
        if (n < NN) {
#pragma unroll
            for (int c = 0; c < 4; c++) {
                int j = j0 + tx * 4 + c;
                outp[n * HID + j] = acc[r][c] + bp[j];
            }
        }
    }
}

// ---------------- edge aggregation: one warp per dst node ----------------
// lane l: head h = l>>3, channels col = h*32 + (l&7)*4 .. +3. Online softmax.
__global__ void k_edge(const float* __restrict__ attL,
                       const float* __restrict__ biasL,
                       const float* __restrict__ xprev,
                       float* __restrict__ xout,
                       int add_res) {
    int wid = blockIdx.x * (blockDim.x >> 5) + (threadIdx.x >> 5);
    if (wid >= NN) return;
    int lane = threadIdx.x & 31;
    int h = lane >> 3;
    int col = h * 32 + (lane & 7) * 4;
    int d = wid;

    float4 xr4 = *(const float4*)&g_xr[d * HID + col];
    float4 a4 = *(const float4*)&attL[col];

    float m = -3.402823466e38f;
    float s = 0.f;
    float ax = 0.f, ay = 0.f, az = 0.f, aw = 0.f;

    int beg = g_rowptr[d], end = g_rowptr[d + 1];
    for (int p = beg; p < end; p++) {
        int src = g_csrc[p];
        float4 xl4 = *(const float4*)&g_xl[src * HID + col];
        float e0 = xl4.x + xr4.x; e0 = fmaxf(e0, 0.2f * e0);
        float e1 = xl4.y + xr4.y; e1 = fmaxf(e1, 0.2f * e1);
        float e2 = xl4.z + xr4.z; e2 = fmaxf(e2, 0.2f * e2);
        float e3 = xl4.w + xr4.w; e3 = fmaxf(e3, 0.2f * e3);
        float r = a4.x * e0 + a4.y * e1 + a4.z * e2 + a4.w * e3;
        r += __shfl_xor_sync(0xffffffffu, r, 1);
        r += __shfl_xor_sync(0xffffffffu, r, 2);
        r += __shfl_xor_sync(0xffffffffu, r, 4);
        // online softmax update
        float mn = fmaxf(m, r);
        float sc = __expf(m - mn);     // first edge: exp(-FLT_MAX) = 0
        float pp = __expf(r - mn);
        s = s * sc + pp;
        ax = ax * sc + pp * xl4.x;
        ay = ay * sc + pp * xl4.y;
        az = az * sc + pp * xl4.z;
        aw = aw * sc + pp * xl4.w;
        m = mn;
    }
    float inv = (s > 0.f) ? (1.f / s) : 0.f;
    float4 b4 = *(const float4*)&biasL[col];
    float o0 = fmaxf(ax * inv + b4.x, 0.f);
    float o1 = fmaxf(ay * inv + b4.y, 0.f);
    float o2 = fmaxf(az * inv + b4.z, 0.f);
    float o3 = fmaxf(aw * inv + b4.w, 0.f);
    if (add_res) {
        float4 rprev = *(const float4*)&xprev[d * HID + col];
        o0 += rprev.x; o1 += rprev.y; o2 += rprev.z; o3 += rprev.w;
    }
    float4 o = make_float4(o0, o1, o2, o3);
    *(float4*)&xout[d * HID + col] = o;
}

// ---------------- graph pooling: mean + max per column ----------------
__global__ void k_out_init(float* out) {
    int i = threadIdx.x;
    if (i < 256) out[i] = 0.f;
}
__global__ void k_reduce(const float* __restrict__ x, float* __restrict__ out) {
    int col = threadIdx.x & 127;
    int rg = threadIdx.x >> 7;  // 0..1
    float s = 0.f, mx = 0.f;    // x >= 0 always (relu + nonneg residual)
    for (int row = blockIdx.x * 2 + rg; row < NN; row += gridDim.x * 2) {
        float v = x[row * HID + col];
        s += v;
        mx = fmaxf(mx, v);
    }
    atomicAdd(&out[col], s);
    atomicMax((int*)&out[HID + col], __float_as_int(mx));
}
__global__ void k_scale(float* out) {
    int i = threadIdx.x;
    if (i < HID) out[i] *= (1.0f / (float)NN);
}

// ---------------- launch ----------------
extern "C" void kernel_launch(void* const* d_in, const int* in_sizes, int n_in,
                              void* d_out, int out_size) {
    const float* feat = (const float*)d_in[0];
    const int* ei = (const int*)d_in[1];
    int base = 2;
    if (n_in >= 11 || (n_in > 2 && in_sizes[2] == 1)) base = 3;
    const float* Wemb = (const float*)d_in[base + 0];
    const float* bemb = (const float*)d_in[base + 1];
    // Wl (unused directly beyond transpose), bl, Wr, br, att, bias
    const float* Wl = (const float*)d_in[base + 2];
    const float* bl = (const float*)d_in[base + 3];
    const float* Wr = (const float*)d_in[base + 4];
    const float* br = (const float*)d_in[base + 5];
    const float* att = (const float*)d_in[base + 6];
    const float* bias = (const float*)d_in[base + 7];
    float* out = (float*)d_out;

    float *xA, *xB;
    cudaGetSymbolAddress((void**)&xA, g_xA);
    cudaGetSymbolAddress((void**)&xB, g_xB);

    float* xfinal = (out_size >= 256 + NN * HID) ? (out + 256) : xA;

    // prep: weight transpose + CSR build
    {
        int tot = LAYERS * HID * HID + HID * 11;
        k_prep<<<(tot + 255) / 256, 256>>>(Wemb, Wl, Wr);
    }
    k_zero_deg<<<(NN + 255) / 256, 256>>>();
    k_hist<<<(EE + 255) / 256, 256>>>(ei);
    k_scan<<<1, 1024>>>();
    k_scatter<<<(EE + 255) / 256, 256>>>(ei);

    // embedding
    k_embed<<<(NN * HID + 255) / 256, 256>>>(feat, bemb, xA);

    // layers
    const float* xin = xA;
    dim3 ggrid((NN + 63) / 64, 4);
    for (int i = 0; i < LAYERS; i++) {
        k_gemm<<<ggrid, 256>>>(xin, bl, br, i);
        float* xo;
        if (i == 3) xo = xfinal;
        else xo = (i & 1) ? xA : xB;
        k_edge<<<(NN + 7) / 8, 256>>>(att + i * HID, bias + i * HID, xin, xo, (i > 0) ? 1 : 0);
        xin = xo;
    }

    // pooling
    k_out_init<<<1, 256>>>(out);
    k_reduce<<<512, 256>>>(xfinal, out);
    k_scale<<<1, 128>>>(out);
}

// round 2
// speedup vs baseline: 1.2225x; 1.2225x over previous
#include <cuda_runtime.h>
#include <cuda_bf16.h>
#include <math.h>

#define NN 50000
#define EE 800000
#define HID 128
#define LAYERS 4

// ---------------- device scratch ----------------
__device__ __align__(16) float g_xA[NN * HID];
__device__ __align__(16) float g_xB[NN * HID];
__device__ __align__(16) float g_xl[NN * HID];
__device__ __align__(16) float g_xr[NN * HID];
__device__ __align__(16) float g_WlT[LAYERS * HID * HID];
__device__ __align__(16) float g_WrT[LAYERS * HID * HID];
__device__ float g_WembT[11 * HID];
__device__ int g_deg[NN];
__device__ int g_rowptr[NN + 1];
__device__ int g_next[NN];
__device__ int g_csrc[EE];
__device__ int g_part[256];
__device__ int g_poff[256];

__device__ __forceinline__ void fma2(unsigned long long& d, unsigned long long a,
                                     unsigned long long b) {
    asm("fma.rn.f32x2 %0, %1, %2, %0;" : "+l"(d) : "l"(a), "l"(b));
}

// ---------------- prep: weight transpose + zero deg + zero out ----------------
__global__ void k_prep(const float* __restrict__ Wemb,
                       const float* __restrict__ Wl,
                       const float* __restrict__ Wr,
                       float* __restrict__ out) {
    int t = blockIdx.x * blockDim.x + threadIdx.x;
    const int per = LAYERS * HID * HID;
    if (t < per) {
        int l = t >> 14, r = t & 16383, j = r >> 7, k = r & 127;
        g_WlT[(l << 14) + k * HID + j] = Wl[t];
        g_WrT[(l << 14) + k * HID + j] = Wr[t];
    } else if (t - per < HID * 11) {
        int u = t - per;
        int j = u / 11, k = u % 11;
        g_WembT[k * HID + j] = Wemb[u];
    }
    if (t < NN) g_deg[t] = 0;
    if (t < 256) out[t] = 0.f;
}

// ---------------- CSR build ----------------
__global__ void k_hist(const int* __restrict__ ei) {
    int e = blockIdx.x * blockDim.x + threadIdx.x;
    if (e < EE) atomicAdd(&g_deg[ei[EE + e]], 1);
}

__global__ void k_scan1() {
    __shared__ int sh[8];
    int b = blockIdx.x, t = threadIdx.x;
    int i = b * 256 + t;
    int v = (i < NN) ? g_deg[i] : 0;
#pragma unroll
    for (int o = 16; o; o >>= 1) v += __shfl_xor_sync(0xffffffffu, v, o);
    if ((t & 31) == 0) sh[t >> 5] = v;
    __syncthreads();
    if (t == 0) {
        int s = 0;
#pragma unroll
        for (int i2 = 0; i2 < 8; i2++) s += sh[i2];
        g_part[b] = s;
    }
}

__global__ void k_scan2(int nb) {
    __shared__ int wsum[8];
    int t = threadIdx.x;
    int v = (t < nb) ? g_part[t] : 0;
    int lane = t & 31, w = t >> 5;
    int x = v;
#pragma unroll
    for (int o = 1; o < 32; o <<= 1) {
        int y = __shfl_up_sync(0xffffffffu, x, o);
        if (lane >= o) x += y;
    }
    if (lane == 31) wsum[w] = x;
    __syncthreads();
    if (t == 0) {
        int run = 0;
#pragma unroll
        for (int i = 0; i < 8; i++) { int tmp = wsum[i]; wsum[i] = run; run += tmp; }
        g_rowptr[NN] = EE;
    }
    __syncthreads();
    g_poff[t] = x - v + wsum[w];
}

__global__ void k_scan3() {
    __shared__ int wsum[8];
    int b = blockIdx.x, t = threadIdx.x;
    int i = b * 256 + t;
    int v = (i < NN) ? g_deg[i] : 0;
    int lane = t & 31, w = t >> 5;
    int x = v;
#pragma unroll
    for (int o = 1; o < 32; o <<= 1) {
        int y = __shfl_up_sync(0xffffffffu, x, o);
        if (lane >= o) x += y;
    }
    if (lane == 31) wsum[w] = x;
    __syncthreads();
    if (t == 0) {
        int run = 0;
#pragma unroll
        for (int i2 = 0; i2 < 8; i2++) { int tmp = wsum[i2]; wsum[i2] = run; run += tmp; }
    }
    __syncthreads();
    int excl = x - v + wsum[w] + g_poff[b];
    if (i < NN) { g_rowptr[i] = excl; g_next[i] = excl; }
}

__global__ void k_scatter(const int* __restrict__ ei) {
    int e = blockIdx.x * blockDim.x + threadIdx.x;
    if (e < EE) {
        int d = ei[EE + e];
        int pos = atomicAdd(&g_next[d], 1);
        g_csrc[pos] = ei[e];
    }
}

// ---------------- embedding ----------------
__global__ void k_embed(const float* __restrict__ feat,
                        const float* __restrict__ bemb,
                        float* __restrict__ xout) {
    int gid = blockIdx.x * blockDim.x + threadIdx.x;
    if (gid >= NN * HID) return;
    int n = gid >> 7, j = gid & 127;
    float a = bemb[j];
#pragma unroll
    for (int k = 0; k < 11; k++) a += feat[n * 11 + k] * g_WembT[k * HID + j];
    xout[gid] = fmaxf(a, 0.f);
}

// ---------------- GEMM with packed f32x2 ----------------
// 128x128 tile, 256 threads, 8x8 per thread, K-chunk 16.
// A-tile stored duplicated as float2 so FFMA2 operands come straight from LDS.
__global__ __launch_bounds__(256, 2) void k_gemm2(const float* __restrict__ xin,
                                                  const float* __restrict__ bl,
                                                  const float* __restrict__ br,
                                                  int layer) {
    __shared__ __align__(16) float2 xs[16][130];
    __shared__ __align__(16) float ws[16][132];
    int n0 = blockIdx.x * 128;
    int side = blockIdx.y;
    const float* Wt = (side ? g_WrT : g_WlT) + (layer << 14);
    float* outp = side ? g_xr : g_xl;
    const float* bp = (side ? br : bl) + layer * HID;
    int tid = threadIdx.x;
    int tx = tid & 15, ty = tid >> 4;

    unsigned long long acc[8][4];
#pragma unroll
    for (int r = 0; r < 8; r++)
#pragma unroll
        for (int c = 0; c < 4; c++) acc[r][c] = 0ull;

    for (int kc = 0; kc < HID; kc += 16) {
#pragma unroll
        for (int it = 0; it < 2; it++) {
            int idx = tid + it * 256;
            int row = idx >> 2, c4 = idx & 3;
            int n = n0 + row;
            float4 v = (n < NN) ? *(const float4*)&xin[n * HID + kc + c4 * 4]
                                : make_float4(0.f, 0.f, 0.f, 0.f);
            xs[c4 * 4 + 0][row] = make_float2(v.x, v.x);
            xs[c4 * 4 + 1][row] = make_float2(v.y, v.y);
            xs[c4 * 4 + 2][row] = make_float2(v.z, v.z);
            xs[c4 * 4 + 3][row] = make_float2(v.w, v.w);
        }
#pragma unroll
        for (int it = 0; it < 2; it++) {
            int idx = tid + it * 256;
            int kk = idx >> 5, c4 = idx & 31;
            *(float4*)&ws[kk][c4 * 4] = *(const float4*)&Wt[(kc + kk) * HID + c4 * 4];
        }
        __syncthreads();
#pragma unroll
        for (int kk = 0; kk < 16; kk++) {
            const ulonglong2* ap = (const ulonglong2*)&xs[kk][ty * 8];
            ulonglong2 a01 = ap[0];
            ulonglong2 a23 = ap[1];
            ulonglong2 a45 = ap[2];
            ulonglong2 a67 = ap[3];
            const ulonglong2* bpc = (const ulonglong2*)&ws[kk][tx * 8];
            ulonglong2 b01 = bpc[0];
            ulonglong2 b23 = bpc[1];
            unsigned long long a[8] = {a01.x, a01.y, a23.x, a23.y,
                                       a45.x, a45.y, a67.x, a67.y};
            unsigned long long b[4] = {b01.x, b01.y, b23.x, b23.y};
#pragma unroll
            for (int r = 0; r < 8; r++) {
                fma2(acc[r][0], a[r], b[0]);
                fma2(acc[r][1], a[r], b[1]);
                fma2(acc[r][2], a[r], b[2]);
                fma2(acc[r][3], a[r], b[3]);
            }
        }
        __syncthreads();
    }

    float4 bias0 = *(const float4*)&bp[tx * 8];
    float4 bias1 = *(const float4*)&bp[tx * 8 + 4];
#pragma unroll
    for (int r = 0; r < 8; r++) {
        int n = n0 + ty * 8 + r;
        if (n < NN) {
            float2 p0 = *(float2*)&acc[r][0];
            float2 p1 = *(float2*)&acc[r][1];
            float2 p2 = *(float2*)&acc[r][2];
            float2 p3 = *(float2*)&acc[r][3];
            float4 o0 = make_float4(p0.x + bias0.x, p0.y + bias0.y,
                                    p1.x + bias0.z, p1.y + bias0.w);
            float4 o1 = make_float4(p2.x + bias1.x, p2.y + bias1.y,
                                    p3.x + bias1.z, p3.y + bias1.w);
            *(float4*)&outp[n * HID + tx * 8] = o0;
            *(float4*)&outp[n * HID + tx * 8 + 4] = o1;
        }
    }
}

// ---------------- edge aggregation: one warp per dst, 4-way unrolled ----------------
__global__ void k_edge(const float* __restrict__ attL,
                       const float* __restrict__ biasL,
                       const float* __restrict__ xprev,
                       float* __restrict__ xout,
                       int add_res) {
    int wid = blockIdx.x * (blockDim.x >> 5) + (threadIdx.x >> 5);
    if (wid >= NN) return;
    int lane = threadIdx.x & 31;
    int h = lane >> 3;
    int col = h * 32 + (lane & 7) * 4;
    int d = wid;

    float4 xr4 = *(const float4*)&g_xr[d * HID + col];
    float4 a4 = *(const float4*)&attL[col];

    float m = -3.402823466e38f;
    float s = 0.f;
    float ax = 0.f, ay = 0.f, az = 0.f, aw = 0.f;

    int beg = g_rowptr[d], end = g_rowptr[d + 1];
    int p = beg;
    for (; p + 4 <= end; p += 4) {
        int sidx[4];
        float4 v[4];
#pragma unroll
        for (int j = 0; j < 4; j++) sidx[j] = g_csrc[p + j];
#pragma unroll
        for (int j = 0; j < 4; j++)
            v[j] = *(const float4*)&g_xl[sidx[j] * HID + col];
        float rr[4];
#pragma unroll
        for (int j = 0; j < 4; j++) {
            float e0 = v[j].x + xr4.x; e0 = fmaxf(e0, 0.2f * e0);
            float e1 = v[j].y + xr4.y; e1 = fmaxf(e1, 0.2f * e1);
            float e2 = v[j].z + xr4.z; e2 = fmaxf(e2, 0.2f * e2);
            float e3 = v[j].w + xr4.w; e3 = fmaxf(e3, 0.2f * e3);
            rr[j] = a4.x * e0 + a4.y * e1 + a4.z * e2 + a4.w * e3;
        }
#pragma unroll
        for (int j = 0; j < 4; j++) rr[j] += __shfl_xor_sync(0xffffffffu, rr[j], 1);
#pragma unroll
        for (int j = 0; j < 4; j++) rr[j] += __shfl_xor_sync(0xffffffffu, rr[j], 2);
#pragma unroll
        for (int j = 0; j < 4; j++) rr[j] += __shfl_xor_sync(0xffffffffu, rr[j], 4);
        float gm = fmaxf(fmaxf(fmaxf(rr[0], rr[1]), fmaxf(rr[2], rr[3])), m);
        float sc = __expf(m - gm);
        float p0 = __expf(rr[0] - gm);
        float p1 = __expf(rr[1] - gm);
        float p2 = __expf(rr[2] - gm);
        float p3 = __expf(rr[3] - gm);
        s = s * sc + p0 + p1 + p2 + p3;
        ax = ax * sc + p0 * v[0].x + p1 * v[1].x + p2 * v[2].x + p3 * v[3].x;
        ay = ay * sc + p0 * v[0].y + p1 * v[1].y + p2 * v[2].y + p3 * v[3].y;
        az = az * sc + p0 * v[0].z + p1 * v[1].z + p2 * v[2].z + p3 * v[3].z;
        aw = aw * sc + p0 * v[0].w + p1 * v[1].w + p2 * v[2].w + p3 * v[3].w;
        m = gm;
    }
    for (; p < end; p++) {
        int src = g_csrc[p];
        float4 xl4 = *(const float4*)&g_xl[src * HID + col];
        float e0 = xl4.x + xr4.x; e0 = fmaxf(e0, 0.2f * e0);
        float e1 = xl4.y + xr4.y; e1 = fmaxf(e1, 0.2f * e1);
        float e2 = xl4.z + xr4.z; e2 = fmaxf(e2, 0.2f * e2);
        float e3 = xl4.w + xr4.w; e3 = fmaxf(e3, 0.2f * e3);
        float r = a4.x * e0 + a4.y * e1 + a4.z * e2 + a4.w * e3;
        r += __shfl_xor_sync(0xffffffffu, r, 1);
        r += __shfl_xor_sync(0xffffffffu, r, 2);
        r += __shfl_xor_sync(0xffffffffu, r, 4);
        float mn = fmaxf(m, r);
        float sc = __expf(m - mn);
        float pp = __expf(r - mn);
        s = s * sc + pp;
        ax = ax * sc + pp * xl4.x;
        ay = ay * sc + pp * xl4.y;
        az = az * sc + pp * xl4.z;
        aw = aw * sc + pp * xl4.w;
        m = mn;
    }
    float inv = (s > 0.f) ? (1.f / s) : 0.f;
    float4 b4 = *(const float4*)&biasL[col];
    float o0 = fmaxf(ax * inv + b4.x, 0.f);
    float o1 = fmaxf(ay * inv + b4.y, 0.f);
    float o2 = fmaxf(az * inv + b4.z, 0.f);
    float o3 = fmaxf(aw * inv + b4.w, 0.f);
    if (add_res) {
        float4 rprev = *(const float4*)&xprev[d * HID + col];
        o0 += rprev.x; o1 += rprev.y; o2 += rprev.z; o3 += rprev.w;
    }
    *(float4*)&xout[d * HID + col] = make_float4(o0, o1, o2, o3);
}

// ---------------- graph pooling ----------------
__global__ void k_reduce(const float* __restrict__ x, float* __restrict__ out) {
    int col = threadIdx.x & 127;
    int rg = threadIdx.x >> 7;
    float s = 0.f, mx = 0.f;
    for (int row = blockIdx.x * 2 + rg; row < NN; row += gridDim.x * 2) {
        float v = x[row * HID + col];
        s += v;
        mx = fmaxf(mx, v);
    }
    atomicAdd(&out[col], s);
    atomicMax((int*)&out[HID + col], __float_as_int(mx));
}
__global__ void k_scale(float* out) {
    int i = threadIdx.x;
    if (i < HID) out[i] *= (1.0f / (float)NN);
}

// ---------------- launch ----------------
extern "C" void kernel_launch(void* const* d_in, const int* in_sizes, int n_in,
                              void* d_out, int out_size) {
    const float* feat = (const float*)d_in[0];
    const int* ei = (const int*)d_in[1];
    int base = 2;
    if (n_in >= 11 || (n_in > 2 && in_sizes[2] == 1)) base = 3;
    const float* Wemb = (const float*)d_in[base + 0];
    const float* bemb = (const float*)d_in[base + 1];
    const float* Wl = (const float*)d_in[base + 2];
    const float* bl = (const float*)d_in[base + 3];
    const float* Wr = (const float*)d_in[base + 4];
    const float* br = (const float*)d_in[base + 5];
    const float* att = (const float*)d_in[base + 6];
    const float* bias = (const float*)d_in[base + 7];
    float* out = (float*)d_out;

    float *xA, *xB;
    cudaGetSymbolAddress((void**)&xA, g_xA);
    cudaGetSymbolAddress((void**)&xB, g_xB);

    float* xfinal = (out_size >= 256 + NN * HID) ? (out + 256) : xA;

    {
        int tot = LAYERS * HID * HID + HID * 11;
        if (tot < NN) tot = NN;
        k_prep<<<(tot + 255) / 256, 256>>>(Wemb, Wl, Wr, out);
    }
    k_hist<<<(EE + 255) / 256, 256>>>(ei);
    const int NB = (NN + 255) / 256;  // 196
    k_scan1<<<NB, 256>>>();
    k_scan2<<<1, 256>>>(NB);
    k_scan3<<<NB, 256>>>();
    k_scatter<<<(EE + 255) / 256, 256>>>(ei);

    k_embed<<<(NN * HID + 255) / 256, 256>>>(feat, bemb, xA);

    const float* xin = xA;
    dim3 ggrid((NN + 127) / 128, 2);
    for (int i = 0; i < LAYERS; i++) {
        k_gemm2<<<ggrid, 256>>>(xin, bl, br, i);
        float* xo;
        if (i == 3) xo = xfinal;
        else xo = (i & 1) ? xA : xB;
        k_edge<<<(NN + 7) / 8, 256>>>(att + i * HID, bias + i * HID, xin, xo, (i > 0) ? 1 : 0);
        xin = xo;
    }

    k_reduce<<<512, 256>>>(xfinal, out);
    k_scale<<<1, 128>>>(out);
}

// round 4
// speedup vs baseline: 1.5273x; 1.2494x over previous
#include <cuda_runtime.h>
#include <cuda_bf16.h>
#include <math.h>
#include <stdint.h>

#define NN 50000
#define EE 800000
#define HID 128
#define LAYERS 4

// ---------------- device scratch ----------------
__device__ __align__(16) float g_xA[NN * HID];
__device__ __align__(16) float g_xB[NN * HID];
__device__ __align__(16) float g_xl[NN * HID];
__device__ __align__(16) float g_xr[NN * HID];
__device__ __align__(16) __nv_bfloat16 g_Wbhi[LAYERS * 256 * HID];
__device__ __align__(16) __nv_bfloat16 g_Wblo[LAYERS * 256 * HID];
__device__ float g_WembT[11 * HID];
__device__ int g_deg[NN];
__device__ int g_rowptr[NN + 1];
__device__ int g_next[NN];
__device__ __align__(16) int g_csrc[EE];
__device__ int g_part[256];
__device__ int g_poff[256];

// ---------------- prep: W -> bf16 hi/lo, WembT, zero deg/out ----------------
__global__ void k_prep(const float* __restrict__ Wemb,
                       const float* __restrict__ Wl,
                       const float* __restrict__ Wr,
                       float* __restrict__ out) {
    int t = blockIdx.x * blockDim.x + threadIdx.x;
    const int tot = LAYERS * 256 * HID;
    if (t < tot) {
        int l = t >> 15, r = t & 32767, row = r >> 7, k = r & 127;
        float v = (row < 128) ? Wl[(l << 14) + row * 128 + k]
                              : Wr[(l << 14) + (row - 128) * 128 + k];
        __nv_bfloat16 h = __float2bfloat16_rn(v);
        g_Wbhi[t] = h;
        g_Wblo[t] = __float2bfloat16_rn(v - __bfloat162float(h));
    }
    if (t < HID * 11) {
        int j = t / 11, k = t % 11;
        g_WembT[k * HID + j] = Wemb[t];
    }
    if (t < NN) g_deg[t] = 0;
    if (t < 256) out[t] = 0.f;
}

// ---------------- CSR build ----------------
__global__ void k_hist(const int* __restrict__ ei) {
    int e = blockIdx.x * blockDim.x + threadIdx.x;
    if (e < EE) atomicAdd(&g_deg[ei[EE + e]], 1);
}
__global__ void k_scan1() {
    __shared__ int sh[8];
    int b = blockIdx.x, t = threadIdx.x;
    int i = b * 256 + t;
    int v = (i < NN) ? g_deg[i] : 0;
#pragma unroll
    for (int o = 16; o; o >>= 1) v += __shfl_xor_sync(0xffffffffu, v, o);
    if ((t & 31) == 0) sh[t >> 5] = v;
    __syncthreads();
    if (t == 0) {
        int s = 0;
#pragma unroll
        for (int i2 = 0; i2 < 8; i2++) s += sh[i2];
        g_part[b] = s;
    }
}
__global__ void k_scan2(int nb) {
    __shared__ int wsum[8];
    int t = threadIdx.x;
    int v = (t < nb) ? g_part[t] : 0;
    int lane = t & 31, w = t >> 5;
    int x = v;
#pragma unroll
    for (int o = 1; o < 32; o <<= 1) {
        int y = __shfl_up_sync(0xffffffffu, x, o);
        if (lane >= o) x += y;
    }
    if (lane == 31) wsum[w] = x;
    __syncthreads();
    if (t == 0) {
        int run = 0;
#pragma unroll
        for (int i = 0; i < 8; i++) { int tmp = wsum[i]; wsum[i] = run; run += tmp; }
        g_rowptr[NN] = EE;
    }
    __syncthreads();
    g_poff[t] = x - v + wsum[w];
}
__global__ void k_scan3() {
    __shared__ int wsum[8];
    int b = blockIdx.x, t = threadIdx.x;
    int i = b * 256 + t;
    int v = (i < NN) ? g_deg[i] : 0;
    int lane = t & 31, w = t >> 5;
    int x = v;
#pragma unroll
    for (int o = 1; o < 32; o <<= 1) {
        int y = __shfl_up_sync(0xffffffffu, x, o);
        if (lane >= o) x += y;
    }
    if (lane == 31) wsum[w] = x;
    __syncthreads();
    if (t == 0) {
        int run = 0;
#pragma unroll
        for (int i2 = 0; i2 < 8; i2++) { int tmp = wsum[i2]; wsum[i2] = run; run += tmp; }
    }
    __syncthreads();
    int excl = x - v + wsum[w] + g_poff[b];
    if (i < NN) { g_rowptr[i] = excl; g_next[i] = excl; }
}
__global__ void k_scatter(const int* __restrict__ ei) {
    int e = blockIdx.x * blockDim.x + threadIdx.x;
    if (e < EE) {
        int d = ei[EE + e];
        int pos = atomicAdd(&g_next[d], 1);
        g_csrc[pos] = ei[e];
    }
}

// ---------------- embedding ----------------
__global__ void k_embed(const float* __restrict__ feat,
                        const float* __restrict__ bemb,
                        float* __restrict__ xout) {
    int gid = blockIdx.x * blockDim.x + threadIdx.x;
    if (gid >= NN * HID) return;
    int n = gid >> 7, j = gid & 127;
    float a = bemb[j];
#pragma unroll
    for (int k = 0; k < 11; k++) a += feat[n * 11 + k] * g_WembT[k * HID + j];
    xout[gid] = fmaxf(a, 0.f);
}

// ---------------- mma.sync bf16 split-precision GEMM ----------------
// Block: 128 rows x 128 cols (one side: Wl or Wr via blockIdx.y), 8 warps.
// Warp tile 32x64: 2 m16 x 8 n8 tiles, K=128 in 8 k16 steps.
// D += Ah*Bh + Ah*Bl + Al*Bh (split-bf16, ~1e-6 rel err).
#define XROW 136   // bf16 row stride (272B: conflict-free frag loads)

__device__ __forceinline__ void mma16816(float* d, uint32_t a0, uint32_t a1,
                                         uint32_t a2, uint32_t a3,
                                         uint32_t b0, uint32_t b1) {
    asm volatile(
        "mma.sync.aligned.m16n8k16.row.col.f32.bf16.bf16.f32 "
        "{%0,%1,%2,%3}, {%4,%5,%6,%7}, {%8,%9}, {%0,%1,%2,%3};"
        : "+f"(d[0]), "+f"(d[1]), "+f"(d[2]), "+f"(d[3])
        : "r"(a0), "r"(a1), "r"(a2), "r"(a3), "r"(b0), "r"(b1));
}

__global__ __launch_bounds__(256, 1) void k_gemm_mma(const float* __restrict__ xin,
                                                     const float* __restrict__ blp,
                                                     const float* __restrict__ brp,
                                                     const __nv_bfloat16* __restrict__ Whi,
                                                     const __nv_bfloat16* __restrict__ Wlo) {
    extern __shared__ __align__(16) char smem[];
    __nv_bfloat16* sxh = (__nv_bfloat16*)smem;
    __nv_bfloat16* sxl = (__nv_bfloat16*)(smem + 128 * XROW * 2);

    int tid = threadIdx.x;
    int n0 = blockIdx.x * 128;
    int side = blockIdx.y;
    const __nv_bfloat16* Wh = Whi + side * 128 * HID;
    const __nv_bfloat16* Wd = Wlo + side * 128 * HID;
    const float* bias = side ? brp : blp;
    float* outp = side ? g_xr : g_xl;

    // stage x tile as bf16 hi/lo
#pragma unroll
    for (int it = 0; it < 16; it++) {
        int idx = tid + it * 256;          // 0..4095 float4-groups
        int row = idx >> 5, g4 = idx & 31;
        int n = n0 + row;
        float4 v = (n < NN) ? *(const float4*)&xin[n * HID + g4 * 4]
                            : make_float4(0.f, 0.f, 0.f, 0.f);
        __nv_bfloat162 h0 = __floats2bfloat162_rn(v.x, v.y);
        __nv_bfloat162 h1 = __floats2bfloat162_rn(v.z, v.w);
        __nv_bfloat162 l0 = __floats2bfloat162_rn(v.x - __bfloat162float(h0.x),
                                                  v.y - __bfloat162float(h0.y));
        __nv_bfloat162 l1 = __floats2bfloat162_rn(v.z - __bfloat162float(h1.x),
                                                  v.w - __bfloat162float(h1.y));
        uint32_t off = row * XROW + g4 * 4;
        *(uint2*)&sxh[off] = make_uint2(*(uint32_t*)&h0, *(uint32_t*)&h1);
        *(uint2*)&sxl[off] = make_uint2(*(uint32_t*)&l0, *(uint32_t*)&l1);
    }
    __syncthreads();

    int wid = tid >> 5, lane = tid & 31;
    int wm = wid & 3, wn = wid >> 2;           // warp tile: rows wm*32, cols wn*64
    int g = lane >> 2, tg = lane & 3;

    float acc[2][8][4];
#pragma unroll
    for (int mt = 0; mt < 2; mt++)
#pragma unroll
        for (int nt = 0; nt < 8; nt++)
#pragma unroll
            for (int q = 0; q < 4; q++) acc[mt][nt][q] = 0.f;

#pragma unroll
    for (int kk = 0; kk < 8; kk++) {
        int k0 = kk * 16;
        uint32_t ah[2][4], al[2][4];
#pragma unroll
        for (int mt = 0; mt < 2; mt++) {
            int rb = wm * 32 + mt * 16;
            uint32_t o0 = (rb + g) * XROW + k0 + tg * 2;
            uint32_t o1 = (rb + 8 + g) * XROW + k0 + tg * 2;
            ah[mt][0] = *(const uint32_t*)&sxh[o0];
            ah[mt][1] = *(const uint32_t*)&sxh[o1];
            ah[mt][2] = *(const uint32_t*)&sxh[o0 + 8];
            ah[mt][3] = *(const uint32_t*)&sxh[o1 + 8];
            al[mt][0] = *(const uint32_t*)&sxl[o0];
            al[mt][1] = *(const uint32_t*)&sxl[o1];
            al[mt][2] = *(const uint32_t*)&sxl[o0 + 8];
            al[mt][3] = *(const uint32_t*)&sxl[o1 + 8];
        }
#pragma unroll
        for (int half = 0; half < 2; half++) {
            uint32_t bh[4][2], bl[4][2];
#pragma unroll
            for (int q = 0; q < 4; q++) {
                int nt = half * 4 + q;
                int j = wn * 64 + nt * 8 + g;
                const __nv_bfloat16* ph = &Wh[j * HID + k0 + tg * 2];
                const __nv_bfloat16* pl = &Wd[j * HID + k0 + tg * 2];
                bh[q][0] = *(const uint32_t*)ph;
                bh[q][1] = *(const uint32_t*)(ph + 8);
                bl[q][0] = *(const uint32_t*)pl;
                bl[q][1] = *(const uint32_t*)(pl + 8);
            }
#pragma unroll
            for (int q = 0; q < 4; q++) {
                int nt = half * 4 + q;
#pragma unroll
                for (int mt = 0; mt < 2; mt++) {
                    mma16816(acc[mt][nt], ah[mt][0], ah[mt][1], ah[mt][2], ah[mt][3],
                             bh[q][0], bh[q][1]);
                    mma16816(acc[mt][nt], ah[mt][0], ah[mt][1], ah[mt][2], ah[mt][3],
                             bl[q][0], bl[q][1]);
                    mma16816(acc[mt][nt], al[mt][0], al[mt][1], al[mt][2], al[mt][3],
                             bh[q][0], bh[q][1]);
                }
            }
        }
    }

    // epilogue: bias + store
#pragma unroll
    for (int mt = 0; mt < 2; mt++) {
        int rb = n0 + wm * 32 + mt * 16;
#pragma unroll
        for (int nt = 0; nt < 8; nt++) {
            int j = wn * 64 + nt * 8 + tg * 2;
            float2 bv = *(const float2*)&bias[j];
            int r0 = rb + g, r1 = rb + 8 + g;
            if (r0 < NN)
                *(float2*)&outp[r0 * HID + j] =
                    make_float2(acc[mt][nt][0] + bv.x, acc[mt][nt][1] + bv.y);
            if (r1 < NN)
                *(float2*)&outp[r1 * HID + j] =
                    make_float2(acc[mt][nt][2] + bv.x, acc[mt][nt][3] + bv.y);
        }
    }
}

// ---------------- edge aggregation: one warp per dst, no online-max ----------------
__global__ void k_edge(const float* __restrict__ attL,
                       const float* __restrict__ biasL,
                       const float* __restrict__ xprev,
                       float* __restrict__ xout,
                       int add_res) {
    int wid = blockIdx.x * (blockDim.x >> 5) + (threadIdx.x >> 5);
    if (wid >= NN) return;
    int lane = threadIdx.x & 31;
    int h = lane >> 3;
    int col = h * 32 + (lane & 7) * 4;
    int d = wid;

    float4 xr4 = *(const float4*)&g_xr[d * HID + col];
    float4 a4 = *(const float4*)&attL[col];

    float s = 0.f;
    float ax = 0.f, ay = 0.f, az = 0.f, aw = 0.f;

    int beg = g_rowptr[d], end = g_rowptr[d + 1];
    int p = beg;
    for (; p < end && (p & 3); p++) {
        int src = g_csrc[p];
        float4 v = *(const float4*)&g_xl[src * HID + col];
        float e0 = v.x + xr4.x; e0 = fmaxf(e0, 0.2f * e0);
        float e1 = v.y + xr4.y; e1 = fmaxf(e1, 0.2f * e1);
        float e2 = v.z + xr4.z; e2 = fmaxf(e2, 0.2f * e2);
        float e3 = v.w + xr4.w; e3 = fmaxf(e3, 0.2f * e3);
        float r = a4.x * e0 + a4.y * e1 + a4.z * e2 + a4.w * e3;
        r += __shfl_xor_sync(0xffffffffu, r, 1);
        r += __shfl_xor_sync(0xffffffffu, r, 2);
        r += __shfl_xor_sync(0xffffffffu, r, 4);
        float pp = __expf(r);
        s += pp;
        ax += pp * v.x; ay += pp * v.y; az += pp * v.z; aw += pp * v.w;
    }
    for (; p + 4 <= end; p += 4) {
        int4 s4 = *(const int4*)&g_csrc[p];
        float4 v[4];
        v[0] = *(const float4*)&g_xl[s4.x * HID + col];
        v[1] = *(const float4*)&g_xl[s4.y * HID + col];
        v[2] = *(const float4*)&g_xl[s4.z * HID + col];
        v[3] = *(const float4*)&g_xl[s4.w * HID + col];
        float rr[4];
#pragma unroll
        for (int j = 0; j < 4; j++) {
            float e0 = v[j].x + xr4.x; e0 = fmaxf(e0, 0.2f * e0);
            float e1 = v[j].y + xr4.y; e1 = fmaxf(e1, 0.2f * e1);
            float e2 = v[j].z + xr4.z; e2 = fmaxf(e2, 0.2f * e2);
            float e3 = v[j].w + xr4.w; e3 = fmaxf(e3, 0.2f * e3);
            rr[j] = a4.x * e0 + a4.y * e1 + a4.z * e2 + a4.w * e3;
        }
#pragma unroll
        for (int j = 0; j < 4; j++) rr[j] += __shfl_xor_sync(0xffffffffu, rr[j], 1);
#pragma unroll
        for (int j = 0; j < 4; j++) rr[j] += __shfl_xor_sync(0xffffffffu, rr[j], 2);
#pragma unroll
        for (int j = 0; j < 4; j++) rr[j] += __shfl_xor_sync(0xffffffffu, rr[j], 4);
        float p0 = __expf(rr[0]);
        float p1 = __expf(rr[1]);
        float p2 = __expf(rr[2]);
        float p3 = __expf(rr[3]);
        s += p0 + p1 + p2 + p3;
        ax += p0 * v[0].x + p1 * v[1].x + p2 * v[2].x + p3 * v[3].x;
        ay += p0 * v[0].y + p1 * v[1].y + p2 * v[2].y + p3 * v[3].y;
        az += p0 * v[0].z + p1 * v[1].z + p2 * v[2].z + p3 * v[3].z;
        aw += p0 * v[0].w + p1 * v[1].w + p2 * v[2].w + p3 * v[3].w;
    }
    for (; p < end; p++) {
        int src = g_csrc[p];
        float4 v = *(const float4*)&g_xl[src * HID + col];
        float e0 = v.x + xr4.x; e0 = fmaxf(e0, 0.2f * e0);
        float e1 = v.y + xr4.y; e1 = fmaxf(e1, 0.2f * e1);
        float e2 = v.z + xr4.z; e2 = fmaxf(e2, 0.2f * e2);
        float e3 = v.w + xr4.w; e3 = fmaxf(e3, 0.2f * e3);
        float r = a4.x * e0 + a4.y * e1 + a4.z * e2 + a4.w * e3;
        r += __shfl_xor_sync(0xffffffffu, r, 1);
        r += __shfl_xor_sync(0xffffffffu, r, 2);
        r += __shfl_xor_sync(0xffffffffu, r, 4);
        float pp = __expf(r);
        s += pp;
        ax += pp * v.x; ay += pp * v.y; az += pp * v.z; aw += pp * v.w;
    }
    float inv = (s > 0.f) ? (1.f / s) : 0.f;
    float4 b4 = *(const float4*)&biasL[col];
    float o0 = fmaxf(ax * inv + b4.x, 0.f);
    float o1 = fmaxf(ay * inv + b4.y, 0.f);
    float o2 = fmaxf(az * inv + b4.z, 0.f);
    float o3 = fmaxf(aw * inv + b4.w, 0.f);
    if (add_res) {
        float4 rp = *(const float4*)&xprev[d * HID + col];
        o0 += rp.x; o1 += rp.y; o2 += rp.z; o3 += rp.w;
    }
    *(float4*)&xout[d * HID + col] = make_float4(o0, o1, o2, o3);
}

// ---------------- graph pooling ----------------
__global__ void k_reduce(const float* __restrict__ x, float* __restrict__ out) {
    int col = threadIdx.x & 127;
    int rg = threadIdx.x >> 7;
    float s = 0.f, mx = 0.f;
    for (int row = blockIdx.x * 2 + rg; row < NN; row += gridDim.x * 2) {
        float v = x[row * HID + col];
        s += v;
        mx = fmaxf(mx, v);
    }
    atomicAdd(&out[col], s);
    atomicMax((int*)&out[HID + col], __float_as_int(mx));
}
__global__ void k_scale(float* out) {
    int i = threadIdx.x;
    if (i < HID) out[i] *= (1.0f / (float)NN);
}

// ---------------- launch ----------------
extern "C" void kernel_launch(void* const* d_in, const int* in_sizes, int n_in,
                              void* d_out, int out_size) {
    const float* feat = (const float*)d_in[0];
    const int* ei = (const int*)d_in[1];
    int base = 2;
    if (n_in >= 11 || (n_in > 2 && in_sizes[2] == 1)) base = 3;
    const float* Wemb = (const float*)d_in[base + 0];
    const float* bemb = (const float*)d_in[base + 1];
    const float* Wl = (const float*)d_in[base + 2];
    const float* bl = (const float*)d_in[base + 3];
    const float* Wr = (const float*)d_in[base + 4];
    const float* br = (const float*)d_in[base + 5];
    const float* att = (const float*)d_in[base + 6];
    const float* bias = (const float*)d_in[base + 7];
    float* out = (float*)d_out;

    float *xA, *xB;
    cudaGetSymbolAddress((void**)&xA, g_xA);
    cudaGetSymbolAddress((void**)&xB, g_xB);
    __nv_bfloat16 *whi, *wlo;
    cudaGetSymbolAddress((void**)&whi, g_Wbhi);
    cudaGetSymbolAddress((void**)&wlo, g_Wblo);

    const int SMEM_GEMM = 128 * XROW * 2 * 2;  // xh + xlo bf16 tiles (69632 B)
    cudaFuncSetAttribute(k_gemm_mma, cudaFuncAttributeMaxDynamicSharedMemorySize, SMEM_GEMM);

    float* xfinal = (out_size >= 256 + NN * HID) ? (out + 256) : xA;

    {
        int tot = LAYERS * 256 * HID;  // 131072 >= NN
        k_prep<<<(tot + 255) / 256, 256>>>(Wemb, Wl, Wr, out);
    }
    k_hist<<<(EE + 255) / 256, 256>>>(ei);
    const int NB = (NN + 255) / 256;
    k_scan1<<<NB, 256>>>();
    k_scan2<<<1, 256>>>(NB);
    k_scan3<<<NB, 256>>>();
    k_scatter<<<(EE + 255) / 256, 256>>>(ei);

    k_embed<<<(NN * HID + 255) / 256, 256>>>(feat, bemb, xA);

    const float* xin = xA;
    const int MT = (NN + 127) / 128;  // 391
    dim3 ggrid(MT, 2);
    for (int i = 0; i < LAYERS; i++) {
        k_gemm_mma<<<ggrid, 256, SMEM_GEMM>>>(xin, bl + i * HID, br + i * HID,
                                              whi + i * 256 * HID, wlo + i * 256 * HID);
        float* xo;
        if (i == 3) xo = xfinal;
        else xo = (i & 1) ? xA : xB;
        k_edge<<<(NN + 7) / 8, 256>>>(att + i * HID, bias + i * HID, xin, xo, (i > 0) ? 1 : 0);
        xin = xo;
    }

    k_reduce<<<512, 256>>>(xfinal, out);
    k_scale<<<1, 128>>>(out);
}